// round 2
// baseline (speedup 1.0000x reference)
#include <cuda_runtime.h>
#include <math.h>

// Problem constants
#define Bv 2
#define Tv 2048
#define Cv 1024
#define HSv 8
#define DSv 32
#define HLv 8
#define DLv 128
#define HDv 64
#define WIN_S 256
#define WIN_L 1024

// ---------------------------------------------------------------------------
// Scratch (static device globals — allocation-free per harness rules)
// ---------------------------------------------------------------------------
__device__ float g_qk_s[Bv * Tv * 2 * HSv * DSv];   // [B,T,512]
__device__ float g_v_s [Bv * Tv * HSv * HDv];       // [B,T,512]
__device__ float g_qk_l[Bv * Tv * 2 * HLv * DLv];   // [B,T,2048]
__device__ float g_v_l [Bv * Tv * HLv * HDv];       // [B,T,512]
__device__ float g_y   [Bv * Tv * Cv];              // [B,T,1024] concat attn out

// ---------------------------------------------------------------------------
// SGEMM: C[M,N] = A[M,K] @ B[K,N], all row-major fp32.
// BM=BN=64, BK=16, 256 threads, 4x4 per thread. Requires M%64==N%64==K%16==0.
// ---------------------------------------------------------------------------
__global__ __launch_bounds__(256) void sgemm_kernel(
    const float* __restrict__ A, const float* __restrict__ B,
    float* __restrict__ C, int M, int N, int K)
{
    __shared__ float As[16][68];   // stored transposed: As[k][m], padded
    __shared__ float Bs[16][64];   // Bs[k][n]

    const int m0 = blockIdx.y * 64;
    const int n0 = blockIdx.x * 64;
    const int t  = threadIdx.x;
    const int tx = t & 15, ty = t >> 4;

    // A tile load indexing: each thread loads one float4 (row ar, k-offset ak)
    const int ar = t >> 2, ak = (t & 3) << 2;
    // B tile load indexing
    const int br = t >> 4, bn = (t & 15) << 2;

    const float* Aptr = A + (size_t)(m0 + ar) * K + ak;
    const float* Bptr = B + (size_t)br * N + n0 + bn;

    float acc[4][4] = {};

    for (int k0 = 0; k0 < K; k0 += 16) {
        float4 av = *(const float4*)(Aptr + k0);
        float4 bv = *(const float4*)(Bptr + (size_t)k0 * N);
        As[ak + 0][ar] = av.x;
        As[ak + 1][ar] = av.y;
        As[ak + 2][ar] = av.z;
        As[ak + 3][ar] = av.w;
        *(float4*)&Bs[br][bn] = bv;
        __syncthreads();

        #pragma unroll
        for (int kk = 0; kk < 16; kk++) {
            float4 a4 = *(const float4*)&As[kk][ty * 4];
            float4 b4 = *(const float4*)&Bs[kk][tx * 4];
            float aa[4] = {a4.x, a4.y, a4.z, a4.w};
            float bb[4] = {b4.x, b4.y, b4.z, b4.w};
            #pragma unroll
            for (int i = 0; i < 4; i++)
                #pragma unroll
                for (int j = 0; j < 4; j++)
                    acc[i][j] += aa[i] * bb[j];
        }
        __syncthreads();
    }

    #pragma unroll
    for (int i = 0; i < 4; i++) {
        float4 o = make_float4(acc[i][0], acc[i][1], acc[i][2], acc[i][3]);
        *(float4*)&C[(size_t)(m0 + ty * 4 + i) * N + n0 + tx * 4] = o;
    }
}

// ---------------------------------------------------------------------------
// Sliding-window flash attention.
//   qk buffer: [B,T, 2*H*D] (first half Q, second half K, per head D)
//   v  buffer: [B,T, H*64]
//   y  buffer: [B,T, 1024], this kernel writes columns [(headOff+h)*64 .. +63]
// One CTA = 16 queries (one warp per query), key tiles of 32 staged in smem.
// ---------------------------------------------------------------------------
template <int D, int W>
__global__ __launch_bounds__(512) void attn_kernel(
    const float* __restrict__ qk, const float* __restrict__ v,
    float* __restrict__ y, int headOff, float scale)
{
    constexpr int BQ = 16, BK = 32, H = 8, DV = 64;
    constexpr int DP = D + 4;

    __shared__ float Qs[BQ][DP];
    __shared__ float Ks[BK][DP];
    __shared__ float Vs[BK][DV];
    __shared__ float Ps[BQ][BK];

    const int t0 = blockIdx.x * BQ;
    const int h  = blockIdx.y;
    const int b  = blockIdx.z;
    const int tid  = threadIdx.x;
    const int w    = tid >> 5;
    const int lane = tid & 31;

    const int qkRow = 2 * H * D;
    const float* qbase = qk + (size_t)b * Tv * qkRow + h * D;
    const float* kbase = qbase + H * D;
    const float* vbase = v + (size_t)b * Tv * (H * DV) + h * DV;

    // Load Q tile (BQ x D) via float4
    for (int i = tid; i < BQ * (D / 4); i += 512) {
        int r = i / (D / 4), c = (i % (D / 4)) * 4;
        *(float4*)&Qs[r][c] = *(const float4*)(qbase + (size_t)(t0 + r) * qkRow + c);
    }

    const int t = t0 + w;               // this warp's query index
    int lo = t0 - (W - 1); if (lo < 0) lo = 0;
    const int kstart = lo & ~(BK - 1);
    const int kend   = t0 + BQ - 1;

    float m = -INFINITY, l = 0.f, acc0 = 0.f, acc1 = 0.f;

    for (int j0 = kstart; j0 <= kend; j0 += BK) {
        __syncthreads();  // prior tile fully consumed (also covers Qs writes)

        // Load K tile (BK x D)
        for (int i = tid; i < BK * (D / 4); i += 512) {
            int r = i / (D / 4), c = (i % (D / 4)) * 4;
            int j = j0 + r;
            float4 kv = make_float4(0.f, 0.f, 0.f, 0.f);
            if (j < Tv) kv = *(const float4*)(kbase + (size_t)j * qkRow + c);
            *(float4*)&Ks[r][c] = kv;
        }
        // Load V tile (BK x 64)
        for (int i = tid; i < BK * (DV / 4); i += 512) {
            int r = i / (DV / 4), c = (i % (DV / 4)) * 4;
            int j = j0 + r;
            float4 vv = make_float4(0.f, 0.f, 0.f, 0.f);
            if (j < Tv) vv = *(const float4*)(vbase + (size_t)j * (H * DV) + c);
            *(float4*)&Vs[r][c] = vv;
        }
        __syncthreads();

        // Scores: lane handles key j0+lane
        const int j = j0 + lane;
        float s = 0.f;
        #pragma unroll
        for (int c = 0; c < D; c += 4) {
            float4 kv = *(const float4*)&Ks[lane][c];
            float4 qv = *(const float4*)&Qs[w][c];   // broadcast
            s += qv.x * kv.x + qv.y * kv.y + qv.z * kv.z + qv.w * kv.w;
        }
        const bool valid = (j <= t) && (t - j < W);
        s = valid ? s * scale : -INFINITY;

        float tmax = s;
        #pragma unroll
        for (int o = 16; o; o >>= 1)
            tmax = fmaxf(tmax, __shfl_xor_sync(0xffffffffu, tmax, o));

        if (tmax != -INFINITY) {
            const float m_new = fmaxf(m, tmax);
            float p = valid ? __expf(s - m_new) : 0.f;
            float psum = p;
            #pragma unroll
            for (int o = 16; o; o >>= 1)
                psum += __shfl_xor_sync(0xffffffffu, psum, o);
            const float alpha = __expf(m - m_new);   // 0 when m == -inf
            l = l * alpha + psum;
            acc0 *= alpha;
            acc1 *= alpha;
            Ps[w][lane] = p;
            __syncwarp();
            #pragma unroll
            for (int jj = 0; jj < BK; jj++) {
                const float pj = Ps[w][jj];          // broadcast
                acc0 += pj * Vs[jj][lane];
                acc1 += pj * Vs[jj][lane + 32];
            }
            m = m_new;
        }
    }

    const float inv = 1.f / l;
    float* yout = y + ((size_t)(b * Tv + t) * Cv) + (headOff + h) * DV;
    yout[lane]      = acc0 * inv;
    yout[lane + 32] = acc1 * inv;
}

// ---------------------------------------------------------------------------
// Launch
// ---------------------------------------------------------------------------
extern "C" void kernel_launch(void* const* d_in, const int* in_sizes, int n_in,
                              void* d_out, int out_size)
{
    const float* x      = (const float*)d_in[0];
    const float* Wqk_s  = (const float*)d_in[1];
    const float* Wv_s   = (const float*)d_in[2];
    const float* Wqk_l  = (const float*)d_in[3];
    const float* Wv_l   = (const float*)d_in[4];
    const float* Wproj  = (const float*)d_in[5];
    float* out = (float*)d_out;

    float *qk_s, *v_s, *qk_l, *v_l, *yb;
    cudaGetSymbolAddress((void**)&qk_s, g_qk_s);
    cudaGetSymbolAddress((void**)&v_s,  g_v_s);
    cudaGetSymbolAddress((void**)&qk_l, g_qk_l);
    cudaGetSymbolAddress((void**)&v_l,  g_v_l);
    cudaGetSymbolAddress((void**)&yb,   g_y);

    const int M = Bv * Tv;       // 4096
    const int K = Cv;            // 1024

    // Projections
    sgemm_kernel<<<dim3((2 * HSv * DSv) / 64, M / 64), 256>>>(x, Wqk_s, qk_s, M, 2 * HSv * DSv, K);
    sgemm_kernel<<<dim3((HSv * HDv)     / 64, M / 64), 256>>>(x, Wv_s,  v_s,  M, HSv * HDv,     K);
    sgemm_kernel<<<dim3((2 * HLv * DLv) / 64, M / 64), 256>>>(x, Wqk_l, qk_l, M, 2 * HLv * DLv, K);
    sgemm_kernel<<<dim3((HLv * HDv)     / 64, M / 64), 256>>>(x, Wv_l,  v_l,  M, HLv * HDv,     K);

    // Attention (short heads -> y cols [0,512), long heads -> [512,1024))
    dim3 agrid(Tv / 16, 8, Bv);
    attn_kernel<DSv, WIN_S><<<agrid, 512>>>(qk_s, v_s, yb, 0,   rsqrtf((float)DSv));
    attn_kernel<DLv, WIN_L><<<agrid, 512>>>(qk_l, v_l, yb, HSv, rsqrtf((float)DLv));

    // Output projection
    sgemm_kernel<<<dim3(Cv / 64, M / 64), 256>>>(yb, Wproj, out, M, Cv, K);
}

// round 4
// speedup vs baseline: 1.1499x; 1.1499x over previous
#include <cuda_runtime.h>
#include <math.h>

// Problem constants
#define Bv 2
#define Tv 2048
#define Cv 1024
#define HSv 8
#define DSv 32
#define HLv 8
#define DLv 128
#define HDv 64
#define WIN_S 256
#define WIN_L 1024

// ---------------------------------------------------------------------------
// Scratch (static device globals — allocation-free per harness rules)
// ---------------------------------------------------------------------------
__device__ float g_qk_s[Bv * Tv * 2 * HSv * DSv];   // [B,T,512]
__device__ float g_v_s [Bv * Tv * HSv * HDv];       // [B,T,512]
__device__ float g_qk_l[Bv * Tv * 2 * HLv * DLv];   // [B,T,2048]
__device__ float g_v_l [Bv * Tv * HLv * HDv];       // [B,T,512]
__device__ float g_y   [Bv * Tv * Cv];              // [B,T,1024] concat attn out

// ---------------------------------------------------------------------------
// SGEMM v2: C[M,N] = A[M,K] @ B[K,N], row-major fp32.
// BM=BN=128, BK=16, 256 threads, 8x8 microtile (4+4 split for conflict-free
// LDS.128), double-buffered shared memory.
// Requires M%128==0, N%128==0, K%16==0.
// ---------------------------------------------------------------------------
#define BM 128
#define BN 128
#define BKK 16

__global__ __launch_bounds__(256, 2) void sgemm_kernel(
    const float* __restrict__ A, const float* __restrict__ B,
    float* __restrict__ C, int M, int N, int K)
{
    __shared__ float As[2][BKK][BM + 4];   // transposed: As[k][m]
    __shared__ float Bs[2][BKK][BN];       // Bs[k][n]

    const int t  = threadIdx.x;
    const int m0 = blockIdx.y * BM;
    const int n0 = blockIdx.x * BN;
    const int tx = t & 15;    // column group
    const int ty = t >> 4;    // row group

    const float* Abase = A + (size_t)m0 * K;
    const float* Bbase = B + n0;

    float4 avr[2], bvr[2];

    // ---- preload tile 0 ----
    #pragma unroll
    for (int q = 0; q < 2; q++) {
        int i  = t + q * 256;
        int r  = i >> 2, kc = (i & 3) << 2;
        avr[q] = *(const float4*)(Abase + (size_t)r * K + kc);
        int br = i >> 5, bc = (i & 31) << 2;
        bvr[q] = *(const float4*)(Bbase + (size_t)br * N + bc);
    }
    int buf = 0;
    #pragma unroll
    for (int q = 0; q < 2; q++) {
        int i = t + q * 256;
        int r = i >> 2, kc = (i & 3) << 2;
        As[buf][kc + 0][r] = avr[q].x;
        As[buf][kc + 1][r] = avr[q].y;
        As[buf][kc + 2][r] = avr[q].z;
        As[buf][kc + 3][r] = avr[q].w;
        int br = i >> 5, bc = (i & 31) << 2;
        *(float4*)&Bs[buf][br][bc] = bvr[q];
    }
    __syncthreads();

    float acc[8][8] = {};
    const int nt = K / BKK;

    for (int tile = 0; tile < nt; tile++) {
        if (tile + 1 < nt) {
            const int k0 = (tile + 1) * BKK;
            #pragma unroll
            for (int q = 0; q < 2; q++) {
                int i  = t + q * 256;
                int r  = i >> 2, kc = (i & 3) << 2;
                avr[q] = *(const float4*)(Abase + (size_t)r * K + k0 + kc);
                int br = i >> 5, bc = (i & 31) << 2;
                bvr[q] = *(const float4*)(Bbase + (size_t)(k0 + br) * N + bc);
            }
        }

        #pragma unroll
        for (int kk = 0; kk < BKK; kk++) {
            float a[8], b[8];
            *(float4*)&a[0] = *(const float4*)&As[buf][kk][ty * 4];
            *(float4*)&a[4] = *(const float4*)&As[buf][kk][ty * 4 + 64];
            *(float4*)&b[0] = *(const float4*)&Bs[buf][kk][tx * 4];
            *(float4*)&b[4] = *(const float4*)&Bs[buf][kk][tx * 4 + 64];
            #pragma unroll
            for (int i2 = 0; i2 < 8; i2++)
                #pragma unroll
                for (int j2 = 0; j2 < 8; j2++)
                    acc[i2][j2] += a[i2] * b[j2];
        }

        if (tile + 1 < nt) {
            const int nb = buf ^ 1;
            #pragma unroll
            for (int q = 0; q < 2; q++) {
                int i = t + q * 256;
                int r = i >> 2, kc = (i & 3) << 2;
                As[nb][kc + 0][r] = avr[q].x;
                As[nb][kc + 1][r] = avr[q].y;
                As[nb][kc + 2][r] = avr[q].z;
                As[nb][kc + 3][r] = avr[q].w;
                int br = i >> 5, bc = (i & 31) << 2;
                *(float4*)&Bs[nb][br][bc] = bvr[q];
            }
            __syncthreads();
            buf = nb;
        }
    }

    // ---- write C: rows {ty*4+i, 64+ty*4+i}, cols {tx*4.., 64+tx*4..} ----
    #pragma unroll
    for (int i = 0; i < 8; i++) {
        const int row = m0 + ((i < 4) ? (ty * 4 + i) : (64 + ty * 4 + i - 4));
        float* crow = C + (size_t)row * N + n0;
        float4 o0 = make_float4(acc[i][0], acc[i][1], acc[i][2], acc[i][3]);
        float4 o1 = make_float4(acc[i][4], acc[i][5], acc[i][6], acc[i][7]);
        *(float4*)&crow[tx * 4]      = o0;
        *(float4*)&crow[64 + tx * 4] = o1;
    }
}

// ---------------------------------------------------------------------------
// Sliding-window flash attention v2.
//   qk: [B,T, 2*H*D] (first half Q, second half K per head)
//   v : [B,T, H*64]
//   y : [B,T, 1024]; writes columns [(headOff+h)*64 .. +63]
// One CTA = 32 queries; each of 16 warps handles queries (w, w+16).
// V kept transposed in smem so P@V reads are float4, conflict-free.
// ---------------------------------------------------------------------------
__device__ __forceinline__ float warp_max(float x) {
    #pragma unroll
    for (int o = 16; o; o >>= 1) x = fmaxf(x, __shfl_xor_sync(0xffffffffu, x, o));
    return x;
}
__device__ __forceinline__ float warp_sum(float x) {
    #pragma unroll
    for (int o = 16; o; o >>= 1) x += __shfl_xor_sync(0xffffffffu, x, o);
    return x;
}

template <int D, int W>
__global__ __launch_bounds__(512) void attn_kernel(
    const float* __restrict__ qk, const float* __restrict__ v,
    float* __restrict__ y, int headOff, float scale)
{
    constexpr int BQ = 32, BK = 32, H = 8, DV = 64;
    constexpr int DP = D + 4;

    __shared__ float Qs[BQ][DP];
    __shared__ float Ks[BK][DP];
    __shared__ float VsT[DV][BK + 4];   // transposed V: VsT[dim][key]
    __shared__ float Ps[BQ][BK];

    const int t0   = blockIdx.x * BQ;
    const int h    = blockIdx.y;
    const int b    = blockIdx.z;
    const int tid  = threadIdx.x;
    const int w    = tid >> 5;
    const int lane = tid & 31;

    const int qkRow = 2 * H * D;
    const float* qbase = qk + (size_t)b * Tv * qkRow + h * D;
    const float* kbase = qbase + H * D;
    const float* vbase = v + (size_t)b * Tv * (H * DV) + h * DV;

    // Load Q tile (BQ x D)
    for (int i = tid; i < BQ * (D / 4); i += 512) {
        int r = i / (D / 4), c = (i % (D / 4)) * 4;
        *(float4*)&Qs[r][c] = *(const float4*)(qbase + (size_t)(t0 + r) * qkRow + c);
    }

    const int tA = t0 + w;          // query A
    const int tB = t0 + w + 16;     // query B
    int lo = t0 - (W - 1); if (lo < 0) lo = 0;
    const int kstart = lo & ~(BK - 1);
    const int kend   = t0 + BQ - 1;

    float mA = -INFINITY, lA = 0.f, a0 = 0.f, a1 = 0.f;
    float mB = -INFINITY, lB = 0.f, b0 = 0.f, b1 = 0.f;

    for (int j0 = kstart; j0 <= kend; j0 += BK) {
        __syncthreads();  // previous tile fully consumed (also covers Qs)

        // K tile (BK x D) — indices provably within [0, Tv)
        for (int i = tid; i < BK * (D / 4); i += 512) {
            int r = i / (D / 4), c = (i % (D / 4)) * 4;
            *(float4*)&Ks[r][c] = *(const float4*)(kbase + (size_t)(j0 + r) * qkRow + c);
        }
        // V tile transposed (BK x DV -> VsT[DV][BK])
        for (int i = tid; i < BK * (DV / 4); i += 512) {
            int r = i / (DV / 4), c = (i % (DV / 4)) * 4;
            float4 vv = *(const float4*)(vbase + (size_t)(j0 + r) * (H * DV) + c);
            VsT[c + 0][r] = vv.x;
            VsT[c + 1][r] = vv.y;
            VsT[c + 2][r] = vv.z;
            VsT[c + 3][r] = vv.w;
        }
        __syncthreads();

        // Scores: lane handles key j = j0 + lane, both queries share K fragment
        const int j = j0 + lane;
        float sA = 0.f, sB = 0.f;
        #pragma unroll
        for (int c = 0; c < D; c += 4) {
            float4 kv = *(const float4*)&Ks[lane][c];
            float4 qa = *(const float4*)&Qs[w][c];        // broadcast
            float4 qb = *(const float4*)&Qs[w + 16][c];   // broadcast
            sA += qa.x * kv.x + qa.y * kv.y + qa.z * kv.z + qa.w * kv.w;
            sB += qb.x * kv.x + qb.y * kv.y + qb.z * kv.z + qb.w * kv.w;
        }
        const bool vA = (j <= tA) && (tA - j < W);
        const bool vB = (j <= tB) && (tB - j < W);
        sA = vA ? sA * scale : -INFINITY;
        sB = vB ? sB * scale : -INFINITY;

        const float tmaxA = warp_max(sA);
        const float tmaxB = warp_max(sB);

        if (tmaxA != -INFINITY) {
            const float mn = fmaxf(mA, tmaxA);
            const float p  = vA ? __expf(sA - mn) : 0.f;
            const float ps = warp_sum(p);
            const float al = __expf(mA - mn);
            lA = lA * al + ps; a0 *= al; a1 *= al; mA = mn;
            Ps[w][lane] = p;
        } else {
            Ps[w][lane] = 0.f;
        }
        if (tmaxB != -INFINITY) {
            const float mn = fmaxf(mB, tmaxB);
            const float p  = vB ? __expf(sB - mn) : 0.f;
            const float ps = warp_sum(p);
            const float al = __expf(mB - mn);
            lB = lB * al + ps; b0 *= al; b1 *= al; mB = mn;
            Ps[w + 16][lane] = p;
        } else {
            Ps[w + 16][lane] = 0.f;
        }
        __syncwarp();

        // P @ V: lane owns output dims (lane, lane+32); float4 over keys
        #pragma unroll
        for (int jj = 0; jj < BK; jj += 4) {
            float4 va = *(const float4*)&VsT[lane][jj];
            float4 vb = *(const float4*)&VsT[lane + 32][jj];
            float4 pa = *(const float4*)&Ps[w][jj];        // broadcast
            float4 pb = *(const float4*)&Ps[w + 16][jj];   // broadcast
            a0 += pa.x * va.x + pa.y * va.y + pa.z * va.z + pa.w * va.w;
            a1 += pa.x * vb.x + pa.y * vb.y + pa.z * vb.z + pa.w * vb.w;
            b0 += pb.x * va.x + pb.y * va.y + pb.z * va.z + pb.w * va.w;
            b1 += pb.x * vb.x + pb.y * vb.y + pb.z * vb.z + pb.w * vb.w;
        }
    }

    const float invA = 1.f / lA;
    const float invB = 1.f / lB;
    float* yA = y + ((size_t)(b * Tv + tA) * Cv) + (headOff + h) * DV;
    float* yB = y + ((size_t)(b * Tv + tB) * Cv) + (headOff + h) * DV;
    yA[lane]      = a0 * invA;
    yA[lane + 32] = a1 * invA;
    yB[lane]      = b0 * invB;
    yB[lane + 32] = b1 * invB;
}

// ---------------------------------------------------------------------------
// Launch
// ---------------------------------------------------------------------------
extern "C" void kernel_launch(void* const* d_in, const int* in_sizes, int n_in,
                              void* d_out, int out_size)
{
    const float* x      = (const float*)d_in[0];
    const float* Wqk_s  = (const float*)d_in[1];
    const float* Wv_s   = (const float*)d_in[2];
    const float* Wqk_l  = (const float*)d_in[3];
    const float* Wv_l   = (const float*)d_in[4];
    const float* Wproj  = (const float*)d_in[5];
    float* out = (float*)d_out;

    float *qk_s, *v_s, *qk_l, *v_l, *yb;
    cudaGetSymbolAddress((void**)&qk_s, g_qk_s);
    cudaGetSymbolAddress((void**)&v_s,  g_v_s);
    cudaGetSymbolAddress((void**)&qk_l, g_qk_l);
    cudaGetSymbolAddress((void**)&v_l,  g_v_l);
    cudaGetSymbolAddress((void**)&yb,   g_y);

    const int M = Bv * Tv;       // 4096
    const int K = Cv;            // 1024

    // Projections
    sgemm_kernel<<<dim3((2 * HSv * DSv) / BN, M / BM), 256>>>(x, Wqk_s, qk_s, M, 2 * HSv * DSv, K);
    sgemm_kernel<<<dim3((HSv * HDv)     / BN, M / BM), 256>>>(x, Wv_s,  v_s,  M, HSv * HDv,     K);
    sgemm_kernel<<<dim3((2 * HLv * DLv) / BN, M / BM), 256>>>(x, Wqk_l, qk_l, M, 2 * HLv * DLv, K);
    sgemm_kernel<<<dim3((HLv * HDv)     / BN, M / BM), 256>>>(x, Wv_l,  v_l,  M, HLv * HDv,     K);

    // Attention (short heads -> y cols [0,512), long heads -> [512,1024))
    dim3 agrid(Tv / 32, 8, Bv);
    attn_kernel<DSv, WIN_S><<<agrid, 512>>>(qk_s, v_s, yb, 0,   1.0f / sqrtf((float)DSv));
    attn_kernel<DLv, WIN_L><<<agrid, 512>>>(qk_l, v_l, yb, HSv, 1.0f / sqrtf((float)DLv));

    // Output projection
    sgemm_kernel<<<dim3(Cv / BN, M / BM), 256>>>(yb, Wproj, out, M, Cv, K);
}

// round 8
// speedup vs baseline: 1.9530x; 1.6984x over previous
#include <cuda_runtime.h>
#include <math.h>
#include <stdint.h>

// Problem constants
#define Bv 2
#define Tv 2048
#define Cv 1024
#define HSv 8
#define DSv 32
#define HLv 8
#define DLv 128
#define HDv 64
#define WIN_S 256
#define WIN_L 1024

#define NTOT 3584          // packed projection width: 512 qk_s + 512 v_s + 2048 qk_l + 512 v_l
#define NW   4608          // NTOT + 1024 (Wproj)
#define Kdim 1024
#define Mrows (Bv * Tv)    // 4096

// ---------------------------------------------------------------------------
// Scratch (static device globals — allocation-free per harness rules)
// ---------------------------------------------------------------------------
__device__ float g_xt[Mrows * Kdim];     // tf32-rounded x
__device__ float g_Wt[NW * Kdim];        // transposed/packed tf32-rounded weights [n][k]
__device__ float g_c1[Mrows * NTOT];     // packed qkv activations [m][n]
__device__ float g_y [Mrows * Cv];       // attention output (tf32-rounded) [m][1024]

// ---------------------------------------------------------------------------
// Helpers
// ---------------------------------------------------------------------------
__device__ __forceinline__ uint32_t smem_u32(const void* p) {
    uint32_t a;
    asm("{ .reg .u64 t; cvta.to.shared.u64 t, %1; cvt.u32.u64 %0, t; }" : "=r"(a) : "l"(p));
    return a;
}
__device__ __forceinline__ float to_tf32(float x) {
    uint32_t u;
    asm("cvt.rna.tf32.f32 %0, %1;" : "=r"(u) : "f"(x));
    return __uint_as_float(u);
}
__device__ __forceinline__ void cp16(uint32_t dst, const float* src) {
    asm volatile("cp.async.ca.shared.global [%0], [%1], 16;" :: "r"(dst), "l"(src));
}
__device__ __forceinline__ void mma_tf32(float* d, const uint32_t* a, const uint32_t* b) {
    asm volatile(
        "mma.sync.aligned.m16n8k8.row.col.f32.tf32.tf32.f32 "
        "{%0,%1,%2,%3}, {%4,%5,%6,%7}, {%8,%9}, {%0,%1,%2,%3};"
        : "+f"(d[0]), "+f"(d[1]), "+f"(d[2]), "+f"(d[3])
        : "r"(a[0]), "r"(a[1]), "r"(a[2]), "r"(a[3]), "r"(b[0]), "r"(b[1]));
}

// ---------------------------------------------------------------------------
// x -> tf32-rounded copy
// ---------------------------------------------------------------------------
__global__ __launch_bounds__(256) void cvt_x(const float* __restrict__ in,
                                             float* __restrict__ out)
{
    int i = (blockIdx.x * 256 + threadIdx.x) * 4;
    float4 v = *(const float4*)(in + i);
    v.x = to_tf32(v.x); v.y = to_tf32(v.y); v.z = to_tf32(v.z); v.w = to_tf32(v.w);
    *(float4*)(out + i) = v;
}

// ---------------------------------------------------------------------------
// Weight pack + transpose (+ tf32 rounding): Wt[n][k] = tf32(W*[k][n])
// ---------------------------------------------------------------------------
__global__ __launch_bounds__(256) void pack_weights(
    const float* __restrict__ Wqk_s, const float* __restrict__ Wv_s,
    const float* __restrict__ Wqk_l, const float* __restrict__ Wv_l,
    const float* __restrict__ Wproj, float* __restrict__ Wt)
{
    __shared__ float tile[32][33];
    const int n0 = blockIdx.x * 32;
    const int k0 = blockIdx.y * 32;
    const int tx = threadIdx.x & 31, ty = threadIdx.x >> 5;   // 32 x 8

    const int n = n0 + tx;
    const float* src; int w, c;
    if      (n < 512)  { src = Wqk_s; w = 512;  c = n; }
    else if (n < 1024) { src = Wv_s;  w = 512;  c = n - 512; }
    else if (n < 3072) { src = Wqk_l; w = 2048; c = n - 1024; }
    else if (n < 3584) { src = Wv_l;  w = 512;  c = n - 3072; }
    else               { src = Wproj; w = 1024; c = n - 3584; }

    #pragma unroll
    for (int i = 0; i < 4; i++) {
        int k = k0 + ty + i * 8;
        tile[tx][ty + i * 8] = to_tf32(src[(size_t)k * w + c]);
    }
    __syncthreads();
    #pragma unroll
    for (int i = 0; i < 4; i++) {
        int nn = n0 + ty + i * 8;
        Wt[(size_t)nn * Kdim + k0 + tx] = tile[ty + i * 8][tx];
    }
}

// ---------------------------------------------------------------------------
// tf32 mma.sync GEMM: C[m0:+128, n0:+128] = A[m0:+128, :] @ Bt[n0:+128, :]^T
//   A : row-major [*][1024] (tf32-rounded)
//   Bt: row-major [*][1024] (tf32-rounded; rows are N, cols are K)
//   C : row-major, leading dim ldc
// 256 threads = 8 warps (2 x 4), warp tile 64x32, K chunk 32, cp.async
// double buffering.
// ---------------------------------------------------------------------------
#define KC  32
#define LDT 36                       // padded smem row (floats)
#define TFLT (128 * LDT)             // floats per tile buffer
#define NCHUNK (Kdim / KC)           // 32

__global__ __launch_bounds__(256, 2) void mma_gemm(
    const float* __restrict__ A, const float* __restrict__ Bt,
    float* __restrict__ C, int ldc)
{
    extern __shared__ float smf[];
    // layout: As0 [0,TFLT), As1 [TFLT,2T), Bs0 [2T,3T), Bs1 [3T,4T)
    const uint32_t sb = smem_u32(smf);

    const int tid  = threadIdx.x;
    const int warp = tid >> 5, lane = tid & 31;
    const int wm   = warp & 1;          // 0..1 -> 64-row slab
    const int wn   = warp >> 1;         // 0..3 -> 32-col slab
    const int m0   = blockIdx.y * 128;
    const int n0   = blockIdx.x * 128;

    const float* Ag = A  + (size_t)m0 * Kdim;
    const float* Bg = Bt + (size_t)n0 * Kdim;

    // per-thread load slots: 4 rows x one float4 each, per tile
    const int lr = tid >> 3;            // row 0..31 (stepped by 32)
    const int lc = (tid & 7) * 4;       // float offset 0..28

    auto issue = [&](int k0, int bi) {
        const uint32_t baseA = sb + (uint32_t)bi * TFLT * 4;
        const uint32_t baseB = sb + (uint32_t)(2 + bi) * TFLT * 4;
        #pragma unroll
        for (int q = 0; q < 4; q++) {
            int r = lr + q * 32;
            uint32_t off = (uint32_t)(r * LDT + lc) * 4;
            cp16(baseA + off, Ag + (size_t)r * Kdim + k0 + lc);
            cp16(baseB + off, Bg + (size_t)r * Kdim + k0 + lc);
        }
        asm volatile("cp.async.commit_group;");
    };

    float acc[4][4][4] = {};

    issue(0, 0);
    for (int c = 0; c < NCHUNK; c++) {
        const int bi = c & 1;
        if (c + 1 < NCHUNK) {
            issue((c + 1) * KC, bi ^ 1);
            asm volatile("cp.async.wait_group 1;");
        } else {
            asm volatile("cp.async.wait_group 0;");
        }
        __syncthreads();

        const float* Ab = smf + bi * TFLT;
        const float* Bb = smf + (2 + bi) * TFLT;

        #pragma unroll
        for (int k8 = 0; k8 < KC / 8; k8++) {
            const int kb = k8 * 8;
            uint32_t a[4][4], b[4][2];
            #pragma unroll
            for (int mt = 0; mt < 4; mt++) {
                int r  = wm * 64 + mt * 16 + (lane >> 2);
                int cc = kb + (lane & 3);
                a[mt][0] = __float_as_uint(Ab[r * LDT + cc]);
                a[mt][1] = __float_as_uint(Ab[(r + 8) * LDT + cc]);
                a[mt][2] = __float_as_uint(Ab[r * LDT + cc + 4]);
                a[mt][3] = __float_as_uint(Ab[(r + 8) * LDT + cc + 4]);
            }
            #pragma unroll
            for (int nt = 0; nt < 4; nt++) {
                int nrow = wn * 32 + nt * 8 + (lane >> 2);
                int kk   = kb + (lane & 3);
                b[nt][0] = __float_as_uint(Bb[nrow * LDT + kk]);
                b[nt][1] = __float_as_uint(Bb[nrow * LDT + kk + 4]);
            }
            #pragma unroll
            for (int mt = 0; mt < 4; mt++)
                #pragma unroll
                for (int nt = 0; nt < 4; nt++)
                    mma_tf32(acc[mt][nt], a[mt], b[nt]);
        }
        __syncthreads();
    }

    // epilogue: c0 (r, c) c1 (r, c+1) c2 (r+8, c) c3 (r+8, c+1)
    #pragma unroll
    for (int mt = 0; mt < 4; mt++) {
        const int r = m0 + wm * 64 + mt * 16 + (lane >> 2);
        #pragma unroll
        for (int nt = 0; nt < 4; nt++) {
            const int cn = n0 + wn * 32 + nt * 8 + (lane & 3) * 2;
            float2 lo = make_float2(acc[mt][nt][0], acc[mt][nt][1]);
            float2 hi = make_float2(acc[mt][nt][2], acc[mt][nt][3]);
            *(float2*)&C[(size_t)r * ldc + cn]       = lo;
            *(float2*)&C[(size_t)(r + 8) * ldc + cn] = hi;
        }
    }
}

// ---------------------------------------------------------------------------
// Sliding-window flash attention (reads packed activation buffer, stride NTOT)
//   src: [B*T, NTOT]; q at col qOff+h*D, k at kOff+h*D, v at vOff+h*64
//   y  : [B*T, 1024]; writes columns [(headOff+h)*64 .. +63] (tf32-rounded)
// ---------------------------------------------------------------------------
__device__ __forceinline__ float warp_max(float x) {
    #pragma unroll
    for (int o = 16; o; o >>= 1) x = fmaxf(x, __shfl_xor_sync(0xffffffffu, x, o));
    return x;
}
__device__ __forceinline__ float warp_sum(float x) {
    #pragma unroll
    for (int o = 16; o; o >>= 1) x += __shfl_xor_sync(0xffffffffu, x, o);
    return x;
}

template <int D, int W>
__global__ __launch_bounds__(512) void attn_kernel(
    const float* __restrict__ src, int qOff, int kOff, int vOff,
    float* __restrict__ y, int headOff, float scale)
{
    constexpr int BQ = 32, BK = 32, DV = 64;
    constexpr int DP = D + 4;

    __shared__ float Qs[BQ][DP];
    __shared__ float Ks[BK][DP];
    __shared__ float VsT[DV][BK + 4];
    __shared__ float Ps[BQ][BK];

    const int t0   = blockIdx.x * BQ;
    const int h    = blockIdx.y;
    const int b    = blockIdx.z;
    const int tid  = threadIdx.x;
    const int w    = tid >> 5;
    const int lane = tid & 31;

    const float* rowb  = src + (size_t)b * Tv * NTOT;
    const float* qbase = rowb + qOff + h * D;
    const float* kbase = rowb + kOff + h * D;
    const float* vbase = rowb + vOff + h * DV;

    for (int i = tid; i < BQ * (D / 4); i += 512) {
        int r = i / (D / 4), c = (i % (D / 4)) * 4;
        *(float4*)&Qs[r][c] = *(const float4*)(qbase + (size_t)(t0 + r) * NTOT + c);
    }

    const int tA = t0 + w;
    const int tB = t0 + w + 16;
    int lo = t0 - (W - 1); if (lo < 0) lo = 0;
    const int kstart = lo & ~(BK - 1);
    const int kend   = t0 + BQ - 1;

    float mA = -INFINITY, lA = 0.f, a0 = 0.f, a1 = 0.f;
    float mB = -INFINITY, lB = 0.f, b0 = 0.f, b1 = 0.f;

    for (int j0 = kstart; j0 <= kend; j0 += BK) {
        __syncthreads();

        for (int i = tid; i < BK * (D / 4); i += 512) {
            int r = i / (D / 4), c = (i % (D / 4)) * 4;
            *(float4*)&Ks[r][c] = *(const float4*)(kbase + (size_t)(j0 + r) * NTOT + c);
        }
        for (int i = tid; i < BK * (DV / 4); i += 512) {
            int r = i / (DV / 4), c = (i % (DV / 4)) * 4;
            float4 vv = *(const float4*)(vbase + (size_t)(j0 + r) * NTOT + c);
            VsT[c + 0][r] = vv.x;
            VsT[c + 1][r] = vv.y;
            VsT[c + 2][r] = vv.z;
            VsT[c + 3][r] = vv.w;
        }
        __syncthreads();

        const int j = j0 + lane;
        float sA = 0.f, sB = 0.f;
        #pragma unroll
        for (int c = 0; c < D; c += 4) {
            float4 kv = *(const float4*)&Ks[lane][c];
            float4 qa = *(const float4*)&Qs[w][c];
            float4 qb = *(const float4*)&Qs[w + 16][c];
            sA += qa.x * kv.x + qa.y * kv.y + qa.z * kv.z + qa.w * kv.w;
            sB += qb.x * kv.x + qb.y * kv.y + qb.z * kv.z + qb.w * kv.w;
        }
        const bool vA = (j <= tA) && (tA - j < W);
        const bool vB = (j <= tB) && (tB - j < W);
        sA = vA ? sA * scale : -INFINITY;
        sB = vB ? sB * scale : -INFINITY;

        const float tmaxA = warp_max(sA);
        const float tmaxB = warp_max(sB);

        if (tmaxA != -INFINITY) {
            const float mn = fmaxf(mA, tmaxA);
            const float p  = vA ? __expf(sA - mn) : 0.f;
            const float ps = warp_sum(p);
            const float al = __expf(mA - mn);
            lA = lA * al + ps; a0 *= al; a1 *= al; mA = mn;
            Ps[w][lane] = p;
        } else {
            Ps[w][lane] = 0.f;
        }
        if (tmaxB != -INFINITY) {
            const float mn = fmaxf(mB, tmaxB);
            const float p  = vB ? __expf(sB - mn) : 0.f;
            const float ps = warp_sum(p);
            const float al = __expf(mB - mn);
            lB = lB * al + ps; b0 *= al; b1 *= al; mB = mn;
            Ps[w + 16][lane] = p;
        } else {
            Ps[w + 16][lane] = 0.f;
        }
        __syncwarp();

        #pragma unroll
        for (int jj = 0; jj < BK; jj += 4) {
            float4 va = *(const float4*)&VsT[lane][jj];
            float4 vb = *(const float4*)&VsT[lane + 32][jj];
            float4 pa = *(const float4*)&Ps[w][jj];
            float4 pb = *(const float4*)&Ps[w + 16][jj];
            a0 += pa.x * va.x + pa.y * va.y + pa.z * va.z + pa.w * va.w;
            a1 += pa.x * vb.x + pa.y * vb.y + pa.z * vb.z + pa.w * vb.w;
            b0 += pb.x * va.x + pb.y * va.y + pb.z * va.z + pb.w * va.w;
            b1 += pb.x * vb.x + pb.y * vb.y + pb.z * vb.z + pb.w * vb.w;
        }
    }

    const float invA = 1.f / lA;
    const float invB = 1.f / lB;
    float* yA = y + ((size_t)(b * Tv + tA) * Cv) + (headOff + h) * HDv;
    float* yB = y + ((size_t)(b * Tv + tB) * Cv) + (headOff + h) * HDv;
    yA[lane]      = to_tf32(a0 * invA);
    yA[lane + 32] = to_tf32(a1 * invA);
    yB[lane]      = to_tf32(b0 * invB);
    yB[lane + 32] = to_tf32(b1 * invB);
}

// ---------------------------------------------------------------------------
// Launch
// ---------------------------------------------------------------------------
extern "C" void kernel_launch(void* const* d_in, const int* in_sizes, int n_in,
                              void* d_out, int out_size)
{
    const float* x      = (const float*)d_in[0];
    const float* Wqk_s  = (const float*)d_in[1];
    const float* Wv_s   = (const float*)d_in[2];
    const float* Wqk_l  = (const float*)d_in[3];
    const float* Wv_l   = (const float*)d_in[4];
    const float* Wproj  = (const float*)d_in[5];
    float* out = (float*)d_out;

    float *xt, *wt, *c1, *yb;
    cudaGetSymbolAddress((void**)&xt, g_xt);
    cudaGetSymbolAddress((void**)&wt, g_Wt);
    cudaGetSymbolAddress((void**)&c1, g_c1);
    cudaGetSymbolAddress((void**)&yb, g_y);

    const int SMEM = 4 * TFLT * 4;   // 73728 B
    cudaFuncSetAttribute(mma_gemm, cudaFuncAttributeMaxDynamicSharedMemorySize, SMEM);

    // 1) tf32-round x; pack + transpose + round all weights
    cvt_x<<<Mrows * Kdim / (256 * 4), 256>>>(x, xt);
    pack_weights<<<dim3(NW / 32, Kdim / 32), 256>>>(Wqk_s, Wv_s, Wqk_l, Wv_l, Wproj, wt);

    // 2) fused input projections: c1[4096][3584] = xt @ Wt[0:3584]^T
    mma_gemm<<<dim3(NTOT / 128, Mrows / 128), 256, SMEM>>>(xt, wt, c1, NTOT);

    // 3) attention (short heads -> y cols [0,512), long heads -> [512,1024))
    dim3 agrid(Tv / 32, 8, Bv);
    attn_kernel<DSv, WIN_S><<<agrid, 512>>>(c1, 0,    256,  512,  yb, 0,   1.0f / sqrtf((float)DSv));
    attn_kernel<DLv, WIN_L><<<agrid, 512>>>(c1, 1024, 2048, 3072, yb, HSv, 1.0f / sqrtf((float)DLv));

    // 4) output projection: out = y @ Wproj (Wt rows [3584:4608])
    mma_gemm<<<dim3(Cv / 128, Mrows / 128), 256, SMEM>>>(yb, wt + (size_t)NTOT * Kdim, out, Cv);
}

// round 12
// speedup vs baseline: 1.9596x; 1.0034x over previous
#include <cuda_runtime.h>
#include <math.h>
#include <stdint.h>

// Problem constants
#define Bv 2
#define Tv 2048
#define Cv 1024
#define HSv 8
#define DSv 32
#define HLv 8
#define DLv 128
#define HDv 64
#define WIN_S 256
#define WIN_L 1024

#define NTOT 3584          // packed projection width: 512 qk_s + 512 v_s + 2048 qk_l + 512 v_l
#define NW   4608          // NTOT + 1024 (Wproj)
#define Kdim 1024
#define Mrows (Bv * Tv)    // 4096

// ---------------------------------------------------------------------------
// Scratch (static device globals — allocation-free per harness rules)
// ---------------------------------------------------------------------------
__device__ float g_xt[Mrows * Kdim];     // tf32-rounded x
__device__ float g_Wt[NW * Kdim];        // transposed/packed tf32-rounded weights [n][k]
__device__ float g_c1[Mrows * NTOT];     // packed qkv activations [m][n]
__device__ float g_y [Mrows * Cv];       // attention output (tf32-rounded) [m][1024]

// ---------------------------------------------------------------------------
// Helpers
// ---------------------------------------------------------------------------
__device__ __forceinline__ uint32_t smem_u32(const void* p) {
    uint32_t a;
    asm("{ .reg .u64 t; cvta.to.shared.u64 t, %1; cvt.u32.u64 %0, t; }" : "=r"(a) : "l"(p));
    return a;
}
__device__ __forceinline__ float to_tf32(float x) {
    uint32_t u;
    asm("cvt.rna.tf32.f32 %0, %1;" : "=r"(u) : "f"(x));
    return __uint_as_float(u);
}
__device__ __forceinline__ void cp16(uint32_t dst, const float* src) {
    asm volatile("cp.async.ca.shared.global [%0], [%1], 16;" :: "r"(dst), "l"(src));
}
__device__ __forceinline__ void mma_tf32(float* d, const uint32_t* a, const uint32_t* b) {
    asm volatile(
        "mma.sync.aligned.m16n8k8.row.col.f32.tf32.tf32.f32 "
        "{%0,%1,%2,%3}, {%4,%5,%6,%7}, {%8,%9}, {%0,%1,%2,%3};"
        : "+f"(d[0]), "+f"(d[1]), "+f"(d[2]), "+f"(d[3])
        : "r"(a[0]), "r"(a[1]), "r"(a[2]), "r"(a[3]), "r"(b[0]), "r"(b[1]));
}

// ---------------------------------------------------------------------------
// x -> tf32-rounded copy
// ---------------------------------------------------------------------------
__global__ __launch_bounds__(256) void cvt_x(const float* __restrict__ in,
                                             float* __restrict__ out)
{
    int i = (blockIdx.x * 256 + threadIdx.x) * 4;
    float4 v = *(const float4*)(in + i);
    v.x = to_tf32(v.x); v.y = to_tf32(v.y); v.z = to_tf32(v.z); v.w = to_tf32(v.w);
    *(float4*)(out + i) = v;
}

// ---------------------------------------------------------------------------
// Weight pack + transpose (+ tf32 rounding): Wt[n][k] = tf32(W*[k][n])
// ---------------------------------------------------------------------------
__global__ __launch_bounds__(256) void pack_weights(
    const float* __restrict__ Wqk_s, const float* __restrict__ Wv_s,
    const float* __restrict__ Wqk_l, const float* __restrict__ Wv_l,
    const float* __restrict__ Wproj, float* __restrict__ Wt)
{
    __shared__ float tile[32][33];
    const int n0 = blockIdx.x * 32;
    const int k0 = blockIdx.y * 32;
    const int tx = threadIdx.x & 31, ty = threadIdx.x >> 5;   // 32 x 8

    const int n = n0 + tx;
    const float* src; int w, c;
    if      (n < 512)  { src = Wqk_s; w = 512;  c = n; }
    else if (n < 1024) { src = Wv_s;  w = 512;  c = n - 512; }
    else if (n < 3072) { src = Wqk_l; w = 2048; c = n - 1024; }
    else if (n < 3584) { src = Wv_l;  w = 512;  c = n - 3072; }
    else               { src = Wproj; w = 1024; c = n - 3584; }

    #pragma unroll
    for (int i = 0; i < 4; i++) {
        int k = k0 + ty + i * 8;
        tile[tx][ty + i * 8] = to_tf32(src[(size_t)k * w + c]);
    }
    __syncthreads();
    #pragma unroll
    for (int i = 0; i < 4; i++) {
        int nn = n0 + ty + i * 8;
        Wt[(size_t)nn * Kdim + k0 + tx] = tile[ty + i * 8][tx];
    }
}

// ---------------------------------------------------------------------------
// tf32 mma.sync GEMM: C[m0:+128, n0:+128] = A[m0:+128, :] @ Bt[n0:+128, :]^T
//   A : row-major [*][1024] (tf32-rounded)
//   Bt: row-major [*][1024] (tf32-rounded; rows are N, cols are K)
//   C : row-major, leading dim ldc
// 256 threads = 8 warps (2 x 4), warp tile 64x32, K chunk 32, cp.async
// double buffering.
// ---------------------------------------------------------------------------
#define KC  32
#define LDT 36                       // padded smem row (floats)
#define TFLT (128 * LDT)             // floats per tile buffer
#define NCHUNK (Kdim / KC)           // 32

__global__ __launch_bounds__(256, 2) void mma_gemm(
    const float* __restrict__ A, const float* __restrict__ Bt,
    float* __restrict__ C, int ldc)
{
    extern __shared__ float smf[];
    // layout: As0 [0,TFLT), As1 [TFLT,2T), Bs0 [2T,3T), Bs1 [3T,4T)
    const uint32_t sb = smem_u32(smf);

    const int tid  = threadIdx.x;
    const int warp = tid >> 5, lane = tid & 31;
    const int wm   = warp & 1;          // 0..1 -> 64-row slab
    const int wn   = warp >> 1;         // 0..3 -> 32-col slab
    const int m0   = blockIdx.y * 128;
    const int n0   = blockIdx.x * 128;

    const float* Ag = A  + (size_t)m0 * Kdim;
    const float* Bg = Bt + (size_t)n0 * Kdim;

    // per-thread load slots: 4 rows x one float4 each, per tile
    const int lr = tid >> 3;            // row 0..31 (stepped by 32)
    const int lc = (tid & 7) * 4;       // float offset 0..28

    auto issue = [&](int k0, int bi) {
        const uint32_t baseA = sb + (uint32_t)bi * TFLT * 4;
        const uint32_t baseB = sb + (uint32_t)(2 + bi) * TFLT * 4;
        #pragma unroll
        for (int q = 0; q < 4; q++) {
            int r = lr + q * 32;
            uint32_t off = (uint32_t)(r * LDT + lc) * 4;
            cp16(baseA + off, Ag + (size_t)r * Kdim + k0 + lc);
            cp16(baseB + off, Bg + (size_t)r * Kdim + k0 + lc);
        }
        asm volatile("cp.async.commit_group;");
    };

    float acc[4][4][4] = {};

    issue(0, 0);
    for (int c = 0; c < NCHUNK; c++) {
        const int bi = c & 1;
        if (c + 1 < NCHUNK) {
            issue((c + 1) * KC, bi ^ 1);
            asm volatile("cp.async.wait_group 1;");
        } else {
            asm volatile("cp.async.wait_group 0;");
        }
        __syncthreads();

        const float* Ab = smf + bi * TFLT;
        const float* Bb = smf + (2 + bi) * TFLT;

        #pragma unroll
        for (int k8 = 0; k8 < KC / 8; k8++) {
            const int kb = k8 * 8;
            uint32_t a[4][4], b[4][2];
            #pragma unroll
            for (int mt = 0; mt < 4; mt++) {
                int r  = wm * 64 + mt * 16 + (lane >> 2);
                int cc = kb + (lane & 3);
                a[mt][0] = __float_as_uint(Ab[r * LDT + cc]);
                a[mt][1] = __float_as_uint(Ab[(r + 8) * LDT + cc]);
                a[mt][2] = __float_as_uint(Ab[r * LDT + cc + 4]);
                a[mt][3] = __float_as_uint(Ab[(r + 8) * LDT + cc + 4]);
            }
            #pragma unroll
            for (int nt = 0; nt < 4; nt++) {
                int nrow = wn * 32 + nt * 8 + (lane >> 2);
                int kk   = kb + (lane & 3);
                b[nt][0] = __float_as_uint(Bb[nrow * LDT + kk]);
                b[nt][1] = __float_as_uint(Bb[nrow * LDT + kk + 4]);
            }
            #pragma unroll
            for (int mt = 0; mt < 4; mt++)
                #pragma unroll
                for (int nt = 0; nt < 4; nt++)
                    mma_tf32(acc[mt][nt], a[mt], b[nt]);
        }
        __syncthreads();
    }

    // epilogue: c0 (r, c) c1 (r, c+1) c2 (r+8, c) c3 (r+8, c+1)
    #pragma unroll
    for (int mt = 0; mt < 4; mt++) {
        const int r = m0 + wm * 64 + mt * 16 + (lane >> 2);
        #pragma unroll
        for (int nt = 0; nt < 4; nt++) {
            const int cn = n0 + wn * 32 + nt * 8 + (lane & 3) * 2;
            float2 lo = make_float2(acc[mt][nt][0], acc[mt][nt][1]);
            float2 hi = make_float2(acc[mt][nt][2], acc[mt][nt][3]);
            *(float2*)&C[(size_t)r * ldc + cn]       = lo;
            *(float2*)&C[(size_t)(r + 8) * ldc + cn] = hi;
        }
    }
}

// ---------------------------------------------------------------------------
// Sliding-window flash attention (reads packed activation buffer, stride NTOT)
//   src: [B*T, NTOT]; q at col qOff+h*D, k at kOff+h*D, v at vOff+h*64
//   y  : [B*T, 1024]; writes columns [(headOff+h)*64 .. +63] (tf32-rounded)
// ---------------------------------------------------------------------------
__device__ __forceinline__ float warp_max(float x) {
    #pragma unroll
    for (int o = 16; o; o >>= 1) x = fmaxf(x, __shfl_xor_sync(0xffffffffu, x, o));
    return x;
}
__device__ __forceinline__ float warp_sum(float x) {
    #pragma unroll
    for (int o = 16; o; o >>= 1) x += __shfl_xor_sync(0xffffffffu, x, o);
    return x;
}

template <int D, int W>
__global__ __launch_bounds__(512) void attn_kernel(
    const float* __restrict__ src, int qOff, int kOff, int vOff,
    float* __restrict__ y, int headOff, float scale)
{
    constexpr int BQ = 32, BK = 32, DV = 64;
    constexpr int DP = D + 4;

    __shared__ float Qs[BQ][DP];
    __shared__ float Ks[BK][DP];
    __shared__ float VsT[DV][BK + 4];
    __shared__ float Ps[BQ][BK];

    const int t0   = blockIdx.x * BQ;
    const int h    = blockIdx.y;
    const int b    = blockIdx.z;
    const int tid  = threadIdx.x;
    const int w    = tid >> 5;
    const int lane = tid & 31;

    const float* rowb  = src + (size_t)b * Tv * NTOT;
    const float* qbase = rowb + qOff + h * D;
    const float* kbase = rowb + kOff + h * D;
    const float* vbase = rowb + vOff + h * DV;

    for (int i = tid; i < BQ * (D / 4); i += 512) {
        int r = i / (D / 4), c = (i % (D / 4)) * 4;
        *(float4*)&Qs[r][c] = *(const float4*)(qbase + (size_t)(t0 + r) * NTOT + c);
    }

    const int tA = t0 + w;
    const int tB = t0 + w + 16;
    int lo = t0 - (W - 1); if (lo < 0) lo = 0;
    const int kstart = lo & ~(BK - 1);
    const int kend   = t0 + BQ - 1;

    float mA = -INFINITY, lA = 0.f, a0 = 0.f, a1 = 0.f;
    float mB = -INFINITY, lB = 0.f, b0 = 0.f, b1 = 0.f;

    for (int j0 = kstart; j0 <= kend; j0 += BK) {
        __syncthreads();

        for (int i = tid; i < BK * (D / 4); i += 512) {
            int r = i / (D / 4), c = (i % (D / 4)) * 4;
            *(float4*)&Ks[r][c] = *(const float4*)(kbase + (size_t)(j0 + r) * NTOT + c);
        }
        for (int i = tid; i < BK * (DV / 4); i += 512) {
            int r = i / (DV / 4), c = (i % (DV / 4)) * 4;
            float4 vv = *(const float4*)(vbase + (size_t)(j0 + r) * NTOT + c);
            VsT[c + 0][r] = vv.x;
            VsT[c + 1][r] = vv.y;
            VsT[c + 2][r] = vv.z;
            VsT[c + 3][r] = vv.w;
        }
        __syncthreads();

        const int j = j0 + lane;
        float sA = 0.f, sB = 0.f;
        #pragma unroll
        for (int c = 0; c < D; c += 4) {
            float4 kv = *(const float4*)&Ks[lane][c];
            float4 qa = *(const float4*)&Qs[w][c];
            float4 qb = *(const float4*)&Qs[w + 16][c];
            sA += qa.x * kv.x + qa.y * kv.y + qa.z * kv.z + qa.w * kv.w;
            sB += qb.x * kv.x + qb.y * kv.y + qb.z * kv.z + qb.w * kv.w;
        }
        const bool vA = (j <= tA) && (tA - j < W);
        const bool vB = (j <= tB) && (tB - j < W);
        sA = vA ? sA * scale : -INFINITY;
        sB = vB ? sB * scale : -INFINITY;

        const float tmaxA = warp_max(sA);
        const float tmaxB = warp_max(sB);

        if (tmaxA != -INFINITY) {
            const float mn = fmaxf(mA, tmaxA);
            const float p  = vA ? __expf(sA - mn) : 0.f;
            const float ps = warp_sum(p);
            const float al = __expf(mA - mn);
            lA = lA * al + ps; a0 *= al; a1 *= al; mA = mn;
            Ps[w][lane] = p;
        } else {
            Ps[w][lane] = 0.f;
        }
        if (tmaxB != -INFINITY) {
            const float mn = fmaxf(mB, tmaxB);
            const float p  = vB ? __expf(sB - mn) : 0.f;
            const float ps = warp_sum(p);
            const float al = __expf(mB - mn);
            lB = lB * al + ps; b0 *= al; b1 *= al; mB = mn;
            Ps[w + 16][lane] = p;
        } else {
            Ps[w + 16][lane] = 0.f;
        }
        __syncwarp();

        #pragma unroll
        for (int jj = 0; jj < BK; jj += 4) {
            float4 va = *(const float4*)&VsT[lane][jj];
            float4 vb = *(const float4*)&VsT[lane + 32][jj];
            float4 pa = *(const float4*)&Ps[w][jj];
            float4 pb = *(const float4*)&Ps[w + 16][jj];
            a0 += pa.x * va.x + pa.y * va.y + pa.z * va.z + pa.w * va.w;
            a1 += pa.x * vb.x + pa.y * vb.y + pa.z * vb.z + pa.w * vb.w;
            b0 += pb.x * va.x + pb.y * va.y + pb.z * va.z + pb.w * va.w;
            b1 += pb.x * vb.x + pb.y * vb.y + pb.z * vb.z + pb.w * vb.w;
        }
    }

    const float invA = 1.f / lA;
    const float invB = 1.f / lB;
    float* yA = y + ((size_t)(b * Tv + tA) * Cv) + (headOff + h) * HDv;
    float* yB = y + ((size_t)(b * Tv + tB) * Cv) + (headOff + h) * HDv;
    yA[lane]      = to_tf32(a0 * invA);
    yA[lane + 32] = to_tf32(a1 * invA);
    yB[lane]      = to_tf32(b0 * invB);
    yB[lane + 32] = to_tf32(b1 * invB);
}

// ---------------------------------------------------------------------------
// Launch
// ---------------------------------------------------------------------------
extern "C" void kernel_launch(void* const* d_in, const int* in_sizes, int n_in,
                              void* d_out, int out_size)
{
    const float* x      = (const float*)d_in[0];
    const float* Wqk_s  = (const float*)d_in[1];
    const float* Wv_s   = (const float*)d_in[2];
    const float* Wqk_l  = (const float*)d_in[3];
    const float* Wv_l   = (const float*)d_in[4];
    const float* Wproj  = (const float*)d_in[5];
    float* out = (float*)d_out;

    float *xt, *wt, *c1, *yb;
    cudaGetSymbolAddress((void**)&xt, g_xt);
    cudaGetSymbolAddress((void**)&wt, g_Wt);
    cudaGetSymbolAddress((void**)&c1, g_c1);
    cudaGetSymbolAddress((void**)&yb, g_y);

    const int SMEM = 4 * TFLT * 4;   // 73728 B
    cudaFuncSetAttribute(mma_gemm, cudaFuncAttributeMaxDynamicSharedMemorySize, SMEM);

    // 1) tf32-round x; pack + transpose + round all weights
    cvt_x<<<Mrows * Kdim / (256 * 4), 256>>>(x, xt);
    pack_weights<<<dim3(NW / 32, Kdim / 32), 256>>>(Wqk_s, Wv_s, Wqk_l, Wv_l, Wproj, wt);

    // 2) fused input projections: c1[4096][3584] = xt @ Wt[0:3584]^T
    mma_gemm<<<dim3(NTOT / 128, Mrows / 128), 256, SMEM>>>(xt, wt, c1, NTOT);

    // 3) attention (short heads -> y cols [0,512), long heads -> [512,1024))
    dim3 agrid(Tv / 32, 8, Bv);
    attn_kernel<DSv, WIN_S><<<agrid, 512>>>(c1, 0,    256,  512,  yb, 0,   1.0f / sqrtf((float)DSv));
    attn_kernel<DLv, WIN_L><<<agrid, 512>>>(c1, 1024, 2048, 3072, yb, HSv, 1.0f / sqrtf((float)DLv));

    // 4) output projection: out = y @ Wproj (Wt rows [3584:4608])
    mma_gemm<<<dim3(Cv / 128, Mrows / 128), 256, SMEM>>>(yb, wt + (size_t)NTOT * Kdim, out, Cv);
}